// round 5
// baseline (speedup 1.0000x reference)
#include <cuda_runtime.h>
#include <cuda_fp16.h>
#include <math.h>
#include <stdint.h>

#define NB   4096
#define NE   16
#define DI   1024
#define DH   2048
#define DOUT 1024
#define NSLOT (NB * 2)
#define MAXT 80          // max m-tiles of 128 across all experts (<= 79, pad to 80)

// ---------------- scratch ----------------------------------------------------
__device__ __half g_h[(size_t)NSLOT * DH];
__device__ int    g_perm[NSLOT];
__device__ int    g_counts[NE];
__device__ int    g_cursor[NE];
__device__ int    g_off[NE + 1];
__device__ int    g_tidx[NB * 2];
__device__ float  g_tw[NB * 2];
__device__ int    g_tile_e[MAXT];
__device__ int    g_tile_m[MAXT];

// ---------------- helpers ----------------------------------------------------
__device__ __forceinline__ void ldsm4(uint32_t addr, uint32_t* a) {
    asm volatile("ldmatrix.sync.aligned.m8n8.x4.shared.b16 {%0,%1,%2,%3}, [%4];"
                 : "=r"(a[0]), "=r"(a[1]), "=r"(a[2]), "=r"(a[3]) : "r"(addr));
}
__device__ __forceinline__ void mma_f16(float* d, const uint32_t* a, const uint32_t* b) {
    asm volatile(
        "mma.sync.aligned.m16n8k16.row.col.f32.f16.f16.f32 "
        "{%0,%1,%2,%3}, {%4,%5,%6,%7}, {%8,%9}, {%0,%1,%2,%3};"
        : "+f"(d[0]), "+f"(d[1]), "+f"(d[2]), "+f"(d[3])
        : "r"(a[0]), "r"(a[1]), "r"(a[2]), "r"(a[3]), "r"(b[0]), "r"(b[1]));
}
__device__ __forceinline__ uint32_t h2bits(__half2 h) {
    return *reinterpret_cast<uint32_t*>(&h);
}
__device__ __forceinline__ uint2 cvt2h(float4 v) {
    uint2 u;
    u.x = h2bits(__floats2half2_rn(v.x, v.y));
    u.y = h2bits(__floats2half2_rn(v.z, v.w));
    return u;
}
__device__ __forceinline__ void redf(float* p, float v) {
    asm volatile("red.global.add.f32 [%0], %1;" :: "l"(p), "f"(v) : "memory");
}

// ---------------- zero out + counters ----------------------------------------
__global__ __launch_bounds__(256) void zero_kernel(float* __restrict__ out) {
    int idx = blockIdx.x * 256 + threadIdx.x;
    ((float4*)out)[idx] = make_float4(0.f, 0.f, 0.f, 0.f);
    if (blockIdx.x == 0 && threadIdx.x < NE) {
        g_counts[threadIdx.x] = 0;
        g_cursor[threadIdx.x] = 0;
    }
}

// ---------------- gate (fp32 exact) ------------------------------------------
__global__ __launch_bounds__(128) void gate_kernel(const float* __restrict__ x,
                                                   const float* __restrict__ gw) {
    __shared__ float xs[4][DI];
    __shared__ float sc[4][NE];
    int t0 = blockIdx.x * 4;

    const float4* xsrc = (const float4*)(x + (size_t)t0 * DI);
    float4* xd = (float4*)&xs[0][0];
    #pragma unroll 4
    for (int i = threadIdx.x; i < 4 * DI / 4; i += 128) xd[i] = xsrc[i];
    __syncthreads();

    int warp = threadIdx.x >> 5, lane = threadIdx.x & 31;
    for (int e = warp * 4; e < warp * 4 + 4; ++e) {
        float s0 = 0.f, s1 = 0.f, s2 = 0.f, s3 = 0.f;
        for (int i = lane; i < DI; i += 32) {
            float g = gw[e * DI + i];
            s0 += xs[0][i] * g; s1 += xs[1][i] * g;
            s2 += xs[2][i] * g; s3 += xs[3][i] * g;
        }
        #pragma unroll
        for (int o = 16; o > 0; o >>= 1) {
            s0 += __shfl_xor_sync(0xffffffffu, s0, o);
            s1 += __shfl_xor_sync(0xffffffffu, s1, o);
            s2 += __shfl_xor_sync(0xffffffffu, s2, o);
            s3 += __shfl_xor_sync(0xffffffffu, s3, o);
        }
        if (lane == 0) { sc[0][e] = s0; sc[1][e] = s1; sc[2][e] = s2; sc[3][e] = s3; }
    }
    __syncthreads();

    if (threadIdx.x < 4) {
        int tt = threadIdx.x;
        int tok = t0 + tt;
        float bv = -1e30f; int bi = 0;
        #pragma unroll
        for (int e = 0; e < NE; ++e) {
            float v = sc[tt][e];
            if (v > bv) { bv = v; bi = e; }
        }
        float bv2 = -1e30f; int bi2 = 0;
        #pragma unroll
        for (int e = 0; e < NE; ++e) {
            if (e == bi) continue;
            float v = sc[tt][e];
            if (v > bv2) { bv2 = v; bi2 = e; }
        }
        float e2 = expf(bv2 - bv);
        float inv = 1.0f / (1.0f + e2);
        g_tidx[tok * 2 + 0] = bi;  g_tw[tok * 2 + 0] = inv;
        g_tidx[tok * 2 + 1] = bi2; g_tw[tok * 2 + 1] = e2 * inv;
        atomicAdd(&g_counts[bi], 1);
        atomicAdd(&g_counts[bi2], 1);
    }
}

// ---------------- prefix + tile table ----------------------------------------
__global__ void prefix_kernel() {
    if (threadIdx.x == 0) {
        int s = 0;
        #pragma unroll
        for (int e = 0; e < NE; ++e) { g_off[e] = s; s += g_counts[e]; }
        g_off[NE] = s;
        int nt = 0;
        for (int e = 0; e < NE; ++e)
            for (int m = g_off[e]; m < g_off[e + 1]; m += 128) {
                g_tile_e[nt] = e; g_tile_m[nt] = m; ++nt;
            }
        for (; nt < MAXT; ++nt) g_tile_e[nt] = -1;
    }
}

// ---------------- scatter (two-level, low contention) -------------------------
__global__ __launch_bounds__(256) void scatter_kernel() {
    __shared__ int lcnt[NE];
    __shared__ int lbase[NE];
    int tid = threadIdx.x;
    int tok = blockIdx.x * 256 + tid;
    if (tid < NE) lcnt[tid] = 0;
    __syncthreads();
    int e0 = g_tidx[tok * 2 + 0], e1 = g_tidx[tok * 2 + 1];
    int r0 = atomicAdd(&lcnt[e0], 1);
    int r1 = atomicAdd(&lcnt[e1], 1);
    __syncthreads();
    if (tid < NE) lbase[tid] = atomicAdd(&g_cursor[tid], lcnt[tid]);
    __syncthreads();
    g_perm[g_off[e0] + lbase[e0] + r0] = tok * 2 + 0;
    g_perm[g_off[e1] + lbase[e1] + r1] = tok * 2 + 1;
}

// ---------------- fp16 mma.sync grouped GEMM, BK=64 --------------------------
// CTA tile 128x128, 8 warps (2m x 4n), warp tile 64x32, double-buffered 72KB.
// Row stride 72 halfs -> conflict-free ldmatrix.
// MODE 0: g_h = relu(gather(x) @ w1^T + b1)           (K=DI,  NTOT=DH)
// MODE 1: red.add(out, (g_h @ w2^T + b2) * gate_w)    (K=DH,  NTOT=DOUT)
#define TS 72
#define ABUF_H (128 * TS)           // 9216 halfs per tile
#define STAGE_H (2 * ABUF_H)
#define GEMM_SMEM (2 * STAGE_H * 2) // 73728 bytes

template <int K, int NTOT, int MODE>
__global__ __launch_bounds__(256) void gemm_tc(const float* __restrict__ Ap,
                                               const float* __restrict__ W,
                                               const float* __restrict__ bias,
                                               float* __restrict__ out) {
    extern __shared__ __half smh[];
    __shared__ float bias_s[128];
    const int NC = K / 64;

    int e = g_tile_e[blockIdx.y];
    if (e < 0) return;
    int m0 = g_tile_m[blockIdx.y];
    int mEnd = g_off[e + 1];
    int n0 = blockIdx.x * 128;

    int tid = threadIdx.x, lane = tid & 31, wid = tid >> 5;
    int mw = (wid >> 2) * 64;
    int nw = (wid & 3) * 32;

    if (tid < 128) bias_s[tid] = bias[e * NTOT + n0 + tid];

    // ---- B loader: row = tid>>3 (+32i), col-halves jc=0/1 of 64 floats
    int brow = tid >> 3, bc4 = tid & 7;
    const float* bP[4];
    int sOff[4];                       // half offset of (row, bc4*4)
    #pragma unroll
    for (int i = 0; i < 4; ++i) {
        int row = brow + 32 * i;
        bP[i] = W + (size_t)e * NTOT * K + (size_t)(n0 + row) * K + bc4 * 4;
        sOff[i] = row * TS + bc4 * 4;
    }

    // ---- A loader
    const float* aP[4];
    const __half* aPh[4];
    int aOffH[4];
    if (MODE == 0) {
        #pragma unroll
        for (int i = 0; i < 4; ++i) {
            int row = brow + 32 * i;
            int gRow = m0 + row;
            int cRow = (gRow < mEnd) ? gRow : m0;
            int pair = g_perm[cRow];
            aP[i] = Ap + (size_t)(pair >> 1) * K + bc4 * 4;
        }
    } else {
        #pragma unroll
        for (int i = 0; i < 4; ++i) {
            int row = brow + 32 * i;
            int gRow = m0 + row;
            int cRow = (gRow < mEnd) ? gRow : m0;
            aPh[i] = g_h + (size_t)cRow * K + bc4 * 8;
            aOffH[i] = row * TS + bc4 * 8;
        }
    }

    // ---- fragment addressing
    uint32_t sb = (uint32_t)__cvta_generic_to_shared(smh);
    uint32_t aAddrBase = sb + (uint32_t)(((mw + (lane & 15)) * TS + (lane >> 4) * 8) * 2);
    int bg = lane >> 3;
    int nblk = bg >> 1, khalf = bg & 1;
    uint32_t bAddrBase = sb + (uint32_t)((ABUF_H +
        (nw + nblk * 8 + (lane & 7)) * TS + khalf * 8) * 2);

    float acc[4][4][4];
    #pragma unroll
    for (int mi = 0; mi < 4; ++mi)
        #pragma unroll
        for (int ni = 0; ni < 4; ++ni)
            #pragma unroll
            for (int j = 0; j < 4; ++j) acc[mi][ni][j] = 0.f;

    uint2 hb[4][2];        // B converted prefetch
    uint2 ha[4][2];        // A converted prefetch (MODE 0)
    uint4 qa[4];           // A fp16 prefetch (MODE 1)

    // ---- fetch chunk 0
    #pragma unroll
    for (int i = 0; i < 4; ++i) {
        hb[i][0] = cvt2h(*(const float4*)(bP[i]));
        hb[i][1] = cvt2h(*(const float4*)(bP[i] + 32));
    }
    if (MODE == 0) {
        #pragma unroll
        for (int i = 0; i < 4; ++i) {
            ha[i][0] = cvt2h(*(const float4*)(aP[i]));
            ha[i][1] = cvt2h(*(const float4*)(aP[i] + 32));
        }
    } else {
        #pragma unroll
        for (int i = 0; i < 4; ++i) qa[i] = *(const uint4*)(aPh[i]);
    }
    // ---- store chunk 0 -> buffer 0
    {
        __half* sA = smh;
        __half* sB = smh + ABUF_H;
        #pragma unroll
        for (int i = 0; i < 4; ++i) {
            *(uint2*)(sB + sOff[i]) = hb[i][0];
            *(uint2*)(sB + sOff[i] + 32) = hb[i][1];
        }
        if (MODE == 0) {
            #pragma unroll
            for (int i = 0; i < 4; ++i) {
                *(uint2*)(sA + sOff[i]) = ha[i][0];
                *(uint2*)(sA + sOff[i] + 32) = ha[i][1];
            }
        } else {
            #pragma unroll
            for (int i = 0; i < 4; ++i) *(uint4*)(sA + aOffH[i]) = qa[i];
        }
    }
    __syncthreads();

    for (int s = 0; s < NC; ++s) {
        int b = s & 1;
        if (s + 1 < NC) {
            #pragma unroll
            for (int i = 0; i < 4; ++i) {
                hb[i][0] = cvt2h(*(const float4*)(bP[i] + (s + 1) * 64));
                hb[i][1] = cvt2h(*(const float4*)(bP[i] + (s + 1) * 64 + 32));
            }
            if (MODE == 0) {
                #pragma unroll
                for (int i = 0; i < 4; ++i) {
                    ha[i][0] = cvt2h(*(const float4*)(aP[i] + (s + 1) * 64));
                    ha[i][1] = cvt2h(*(const float4*)(aP[i] + (s + 1) * 64 + 32));
                }
            } else {
                #pragma unroll
                for (int i = 0; i < 4; ++i) qa[i] = *(const uint4*)(aPh[i] + (s + 1) * 64);
            }
        }
        // ---- compute buffer b (4 k-steps of 16)
        uint32_t aA = aAddrBase + (uint32_t)(b * STAGE_H * 2);
        uint32_t bA = bAddrBase + (uint32_t)(b * STAGE_H * 2);
        #pragma unroll
        for (int ks = 0; ks < 4; ++ks) {
            uint32_t af[4][4];
            #pragma unroll
            for (int mi = 0; mi < 4; ++mi)
                ldsm4(aA + mi * (16 * TS * 2) + ks * 32, af[mi]);
            uint32_t bfr[8];
            #pragma unroll
            for (int ni2 = 0; ni2 < 2; ++ni2)
                ldsm4(bA + ni2 * (16 * TS * 2) + ks * 32, &bfr[ni2 * 4]);
            #pragma unroll
            for (int mi = 0; mi < 4; ++mi)
                #pragma unroll
                for (int ni = 0; ni < 4; ++ni)
                    mma_f16(acc[mi][ni], af[mi], &bfr[ni * 2]);
        }
        if (s + 1 < NC) {
            int nb = b ^ 1;
            __half* sA = smh + nb * STAGE_H;
            __half* sB = sA + ABUF_H;
            #pragma unroll
            for (int i = 0; i < 4; ++i) {
                *(uint2*)(sB + sOff[i]) = hb[i][0];
                *(uint2*)(sB + sOff[i] + 32) = hb[i][1];
            }
            if (MODE == 0) {
                #pragma unroll
                for (int i = 0; i < 4; ++i) {
                    *(uint2*)(sA + sOff[i]) = ha[i][0];
                    *(uint2*)(sA + sOff[i] + 32) = ha[i][1];
                }
            } else {
                #pragma unroll
                for (int i = 0; i < 4; ++i) *(uint4*)(sA + aOffH[i]) = qa[i];
            }
            __syncthreads();
        }
    }

    // ---- epilogue
    int r4 = lane >> 2, cc = (lane & 3) * 2;
    #pragma unroll
    for (int mi = 0; mi < 4; ++mi) {
        int row0 = m0 + mw + mi * 16 + r4;
        int row1 = row0 + 8;
        bool v0 = row0 < mEnd, v1 = row1 < mEnd;
        if (MODE == 0) {
            __half* C0 = g_h + (size_t)row0 * NTOT + n0;
            __half* C1 = g_h + (size_t)row1 * NTOT + n0;
            #pragma unroll
            for (int ni = 0; ni < 4; ++ni) {
                int col = nw + ni * 8 + cc;
                float bb0 = bias_s[col], bb1 = bias_s[col + 1];
                const float* d = acc[mi][ni];
                if (v0) {
                    __half2 h = __floats2half2_rn(fmaxf(d[0] + bb0, 0.f),
                                                  fmaxf(d[1] + bb1, 0.f));
                    *(__half2*)&C0[col] = h;
                }
                if (v1) {
                    __half2 h = __floats2half2_rn(fmaxf(d[2] + bb0, 0.f),
                                                  fmaxf(d[3] + bb1, 0.f));
                    *(__half2*)&C1[col] = h;
                }
            }
        } else {
            int p0 = 0, p1 = 0;
            float w0 = 0.f, w1 = 0.f;
            if (v0) { p0 = g_perm[row0]; w0 = g_tw[p0]; }
            if (v1) { p1 = g_perm[row1]; w1 = g_tw[p1]; }
            float* O0 = out + (size_t)(p0 >> 1) * DOUT + n0;
            float* O1 = out + (size_t)(p1 >> 1) * DOUT + n0;
            #pragma unroll
            for (int ni = 0; ni < 4; ++ni) {
                int col = nw + ni * 8 + cc;
                float bb0 = bias_s[col], bb1 = bias_s[col + 1];
                const float* d = acc[mi][ni];
                if (v0) {
                    redf(O0 + col,     (d[0] + bb0) * w0);
                    redf(O0 + col + 1, (d[1] + bb1) * w0);
                }
                if (v1) {
                    redf(O1 + col,     (d[2] + bb0) * w1);
                    redf(O1 + col + 1, (d[3] + bb1) * w1);
                }
            }
        }
    }
}

// ---------------- launch -----------------------------------------------------
extern "C" void kernel_launch(void* const* d_in, const int* in_sizes, int n_in,
                              void* d_out, int out_size) {
    const float* x  = (const float*)d_in[0];
    const float* gw = (const float*)d_in[1];
    const float* w1 = (const float*)d_in[2];
    const float* b1 = (const float*)d_in[3];
    const float* w2 = (const float*)d_in[4];
    const float* b2 = (const float*)d_in[5];
    float* out = (float*)d_out;

    cudaFuncSetAttribute(gemm_tc<DI, DH, 0>,
                         cudaFuncAttributeMaxDynamicSharedMemorySize, GEMM_SMEM);
    cudaFuncSetAttribute(gemm_tc<DH, DOUT, 1>,
                         cudaFuncAttributeMaxDynamicSharedMemorySize, GEMM_SMEM);

    zero_kernel<<<NB * DOUT / 4 / 256, 256>>>(out);
    gate_kernel<<<NB / 4, 128>>>(x, gw);
    prefix_kernel<<<1, 32>>>();
    scatter_kernel<<<NB / 256, 256>>>();
    gemm_tc<DI, DH, 0><<<dim3(DH / 128, MAXT), 256, GEMM_SMEM>>>(x, w1, b1, out);
    gemm_tc<DH, DOUT, 1><<<dim3(DOUT / 128, MAXT), 256, GEMM_SMEM>>>(nullptr, w2, b2, out);
}

// round 6
// speedup vs baseline: 1.5205x; 1.5205x over previous
#include <cuda_runtime.h>
#include <cuda_fp16.h>
#include <math.h>
#include <stdint.h>

#define NB   4096
#define NE   16
#define DI   1024
#define DH   2048
#define DOUT 1024
#define NSLOT (NB * 2)
#define MAXT 80          // max 128-row m-tiles across all experts (<=79, pad 80)

// ---------------- scratch ----------------------------------------------------
__device__ __half g_h[(size_t)NSLOT * DH];         // fp16 hidden activations
__device__ float  g_contrib[(size_t)NSLOT * DOUT];
__device__ int    g_perm[NSLOT];
__device__ int    g_inv[NSLOT];
__device__ int    g_counts[NE];
__device__ int    g_cursor[NE];
__device__ int    g_off[NE + 1];
__device__ int    g_tidx[NB * 2];
__device__ float  g_tw[NB * 2];
__device__ int    g_tile_e[MAXT];
__device__ int    g_tile_m[MAXT];

// ---------------- helpers ----------------------------------------------------
__device__ __forceinline__ void ldsm4(uint32_t addr, uint32_t* a) {
    asm volatile("ldmatrix.sync.aligned.m8n8.x4.shared.b16 {%0,%1,%2,%3}, [%4];"
                 : "=r"(a[0]), "=r"(a[1]), "=r"(a[2]), "=r"(a[3]) : "r"(addr));
}
__device__ __forceinline__ void mma_f16(float* d, const uint32_t* a, const uint32_t* b) {
    asm volatile(
        "mma.sync.aligned.m16n8k16.row.col.f32.f16.f16.f32 "
        "{%0,%1,%2,%3}, {%4,%5,%6,%7}, {%8,%9}, {%0,%1,%2,%3};"
        : "+f"(d[0]), "+f"(d[1]), "+f"(d[2]), "+f"(d[3])
        : "r"(a[0]), "r"(a[1]), "r"(a[2]), "r"(a[3]), "r"(b[0]), "r"(b[1]));
}
__device__ __forceinline__ uint32_t h2bits(__half2 h) {
    return *reinterpret_cast<uint32_t*>(&h);
}

// ---------------- init -------------------------------------------------------
__global__ void init_kernel() {
    int t = threadIdx.x;
    if (t < NE) { g_counts[t] = 0; g_cursor[t] = 0; }
}

// ---------------- gate (fp32 exact — routing must match reference) -----------
__global__ __launch_bounds__(128) void gate_kernel(const float* __restrict__ x,
                                                   const float* __restrict__ gw) {
    __shared__ float xs[4][DI];
    __shared__ float sc[4][NE];
    int t0 = blockIdx.x * 4;

    const float4* xsrc = (const float4*)(x + (size_t)t0 * DI);
    float4* xd = (float4*)&xs[0][0];
    #pragma unroll 4
    for (int i = threadIdx.x; i < 4 * DI / 4; i += 128) xd[i] = xsrc[i];
    __syncthreads();

    int warp = threadIdx.x >> 5, lane = threadIdx.x & 31;
    for (int e = warp * 4; e < warp * 4 + 4; ++e) {
        float s0 = 0.f, s1 = 0.f, s2 = 0.f, s3 = 0.f;
        for (int i = lane; i < DI; i += 32) {
            float g = gw[e * DI + i];
            s0 += xs[0][i] * g; s1 += xs[1][i] * g;
            s2 += xs[2][i] * g; s3 += xs[3][i] * g;
        }
        #pragma unroll
        for (int o = 16; o > 0; o >>= 1) {
            s0 += __shfl_xor_sync(0xffffffffu, s0, o);
            s1 += __shfl_xor_sync(0xffffffffu, s1, o);
            s2 += __shfl_xor_sync(0xffffffffu, s2, o);
            s3 += __shfl_xor_sync(0xffffffffu, s3, o);
        }
        if (lane == 0) { sc[0][e] = s0; sc[1][e] = s1; sc[2][e] = s2; sc[3][e] = s3; }
    }
    __syncthreads();

    if (threadIdx.x < 4) {
        int tt = threadIdx.x;
        int tok = t0 + tt;
        float bv = -1e30f; int bi = 0;
        #pragma unroll
        for (int e = 0; e < NE; ++e) {
            float v = sc[tt][e];
            if (v > bv) { bv = v; bi = e; }
        }
        float bv2 = -1e30f; int bi2 = 0;
        #pragma unroll
        for (int e = 0; e < NE; ++e) {
            if (e == bi) continue;
            float v = sc[tt][e];
            if (v > bv2) { bv2 = v; bi2 = e; }
        }
        float e2 = expf(bv2 - bv);
        float inv = 1.0f / (1.0f + e2);
        g_tidx[tok * 2 + 0] = bi;  g_tw[tok * 2 + 0] = inv;
        g_tidx[tok * 2 + 1] = bi2; g_tw[tok * 2 + 1] = e2 * inv;
        atomicAdd(&g_counts[bi], 1);
        atomicAdd(&g_counts[bi2], 1);
    }
}

// ---------------- prefix + exact tile table ----------------------------------
__global__ void prefix_kernel() {
    if (threadIdx.x == 0) {
        int s = 0;
        #pragma unroll
        for (int e = 0; e < NE; ++e) { g_off[e] = s; s += g_counts[e]; }
        g_off[NE] = s;
        int nt = 0;
        for (int e = 0; e < NE; ++e)
            for (int m = g_off[e]; m < g_off[e + 1]; m += 128) {
                g_tile_e[nt] = e; g_tile_m[nt] = m; ++nt;
            }
        for (; nt < MAXT; ++nt) g_tile_e[nt] = -1;
    }
}

// ---------------- scatter (two-level, low contention) -------------------------
__global__ __launch_bounds__(256) void scatter_kernel() {
    __shared__ int lcnt[NE];
    __shared__ int lbase[NE];
    int tid = threadIdx.x;
    int tok = blockIdx.x * 256 + tid;
    if (tid < NE) lcnt[tid] = 0;
    __syncthreads();
    int e0 = g_tidx[tok * 2 + 0], e1 = g_tidx[tok * 2 + 1];
    int r0 = atomicAdd(&lcnt[e0], 1);
    int r1 = atomicAdd(&lcnt[e1], 1);
    __syncthreads();
    if (tid < NE) lbase[tid] = atomicAdd(&g_cursor[tid], lcnt[tid]);
    __syncthreads();
    int p0 = g_off[e0] + lbase[e0] + r0;
    int p1 = g_off[e1] + lbase[e1] + r1;
    g_perm[p0] = tok * 2 + 0;  g_inv[tok * 2 + 0] = p0;
    g_perm[p1] = tok * 2 + 1;  g_inv[tok * 2 + 1] = p1;
}

// ---------------- fp16 mma.sync grouped GEMM (R4 datapath, tile table) -------
// CTA tile 128x128, BK=32 halfs, double-buffered 40KB (2 CTA/SM).
// A m-major / B n-major in smem, stride 40 halfs.
// MODE 0: g_h = relu(gather(x) @ w1^T + b1)        (K=DI,  NTOT=DH, A fp32)
// MODE 1: g_contrib = (g_h @ w2^T + b2) * gate_w   (K=DH,  NTOT=DOUT, A fp16)
#define TS 40
#define ABUF_H (128 * TS)
#define STAGE_H (2 * ABUF_H)
#define GEMM_SMEM (2 * STAGE_H * 2)   // 40960 bytes

template <int K, int NTOT, int MODE>
__global__ __launch_bounds__(256) void gemm_tc(const float* __restrict__ Ap,
                                               const float* __restrict__ W,
                                               const float* __restrict__ bias) {
    extern __shared__ __half smh[];
    __shared__ float bias_s[128];
    const int NC = K / 32;

    int e = g_tile_e[blockIdx.y];
    if (e < 0) return;
    int m0 = g_tile_m[blockIdx.y];
    int mEnd = g_off[e + 1];
    int n0 = blockIdx.x * 128;

    int tid = threadIdx.x, lane = tid & 31, wid = tid >> 5;
    int mw = (wid >> 2) * 64;
    int nw = (wid & 3) * 32;

    if (tid < 128) bias_s[tid] = bias[e * NTOT + n0 + tid];

    // ---- B loader: row = tid>>3 + 32*i, c4 = tid&7
    int brow = tid >> 3, bc4 = tid & 7;
    const float* bP[4];
    int bOff[4];
    #pragma unroll
    for (int i = 0; i < 4; ++i) {
        int row = brow + 32 * i;
        bP[i] = W + (size_t)e * NTOT * K + (size_t)(n0 + row) * K + bc4 * 4;
        bOff[i] = row * TS + bc4 * 4;
    }

    // ---- A loader
    const float* aP[4];
    const __half* aPh[2];
    int aOff[4], aOffH[2];
    if (MODE == 0) {
        #pragma unroll
        for (int i = 0; i < 4; ++i) {
            int row = brow + 32 * i;
            int gRow = m0 + row;
            int cRow = (gRow < mEnd) ? gRow : m0;
            int pair = g_perm[cRow];
            aP[i] = Ap + (size_t)(pair >> 1) * K + bc4 * 4;
            aOff[i] = row * TS + bc4 * 4;
        }
    } else {
        int arow = tid >> 2, aseg = tid & 3;
        #pragma unroll
        for (int i = 0; i < 2; ++i) {
            int row = arow + 64 * i;
            int gRow = m0 + row;
            int cRow = (gRow < mEnd) ? gRow : m0;
            aPh[i] = g_h + (size_t)cRow * K + aseg * 8;
            aOffH[i] = row * TS + aseg * 8;
        }
    }

    // ---- fragment addressing
    uint32_t sb = (uint32_t)__cvta_generic_to_shared(smh);
    uint32_t aAddrBase = sb + (uint32_t)(((mw + (lane & 15)) * TS + (lane >> 4) * 8) * 2);
    int bg = lane >> 3;
    int nblk = bg >> 1, khalf = bg & 1;
    uint32_t bAddrBase = sb + (uint32_t)((ABUF_H +
        (nw + nblk * 8 + (lane & 7)) * TS + khalf * 8) * 2);

    float acc[4][4][4];
    #pragma unroll
    for (int mi = 0; mi < 4; ++mi)
        #pragma unroll
        for (int ni = 0; ni < 4; ++ni)
            #pragma unroll
            for (int j = 0; j < 4; ++j) acc[mi][ni][j] = 0.f;

    float4 pb[4];
    float4 pa[4];
    uint4 qa[2];

    // ---- fetch + store chunk 0
    #pragma unroll
    for (int i = 0; i < 4; ++i) pb[i] = *(const float4*)(bP[i]);
    if (MODE == 0) {
        #pragma unroll
        for (int i = 0; i < 4; ++i) pa[i] = *(const float4*)(aP[i]);
    } else {
        #pragma unroll
        for (int i = 0; i < 2; ++i) qa[i] = *(const uint4*)(aPh[i]);
    }
    {
        __half* sA = smh;
        __half* sB = smh + ABUF_H;
        #pragma unroll
        for (int i = 0; i < 4; ++i) {
            uint2 u;
            u.x = h2bits(__floats2half2_rn(pb[i].x, pb[i].y));
            u.y = h2bits(__floats2half2_rn(pb[i].z, pb[i].w));
            *(uint2*)(sB + bOff[i]) = u;
        }
        if (MODE == 0) {
            #pragma unroll
            for (int i = 0; i < 4; ++i) {
                uint2 u;
                u.x = h2bits(__floats2half2_rn(pa[i].x, pa[i].y));
                u.y = h2bits(__floats2half2_rn(pa[i].z, pa[i].w));
                *(uint2*)(sA + aOff[i]) = u;
            }
        } else {
            #pragma unroll
            for (int i = 0; i < 2; ++i) *(uint4*)(sA + aOffH[i]) = qa[i];
        }
    }
    __syncthreads();

    for (int s = 0; s < NC; ++s) {
        int b = s & 1;
        if (s + 1 < NC) {
            #pragma unroll
            for (int i = 0; i < 4; ++i) pb[i] = *(const float4*)(bP[i] + (s + 1) * 32);
            if (MODE == 0) {
                #pragma unroll
                for (int i = 0; i < 4; ++i) pa[i] = *(const float4*)(aP[i] + (s + 1) * 32);
            } else {
                #pragma unroll
                for (int i = 0; i < 2; ++i) qa[i] = *(const uint4*)(aPh[i] + (s + 1) * 32);
            }
        }
        // ---- compute on buffer b
        uint32_t aA = aAddrBase + (uint32_t)(b * STAGE_H * 2);
        uint32_t bA = bAddrBase + (uint32_t)(b * STAGE_H * 2);
        #pragma unroll
        for (int ks = 0; ks < 2; ++ks) {
            uint32_t af[4][4];
            #pragma unroll
            for (int mi = 0; mi < 4; ++mi)
                ldsm4(aA + mi * (16 * TS * 2) + ks * 32, af[mi]);
            uint32_t bfr[8];
            #pragma unroll
            for (int ni2 = 0; ni2 < 2; ++ni2)
                ldsm4(bA + ni2 * (16 * TS * 2) + ks * 32, &bfr[ni2 * 4]);
            #pragma unroll
            for (int mi = 0; mi < 4; ++mi)
                #pragma unroll
                for (int ni = 0; ni < 4; ++ni)
                    mma_f16(acc[mi][ni], af[mi], &bfr[ni * 2]);
        }
        if (s + 1 < NC) {
            int nb = b ^ 1;
            __half* sA = smh + nb * STAGE_H;
            __half* sB = sA + ABUF_H;
            #pragma unroll
            for (int i = 0; i < 4; ++i) {
                uint2 u;
                u.x = h2bits(__floats2half2_rn(pb[i].x, pb[i].y));
                u.y = h2bits(__floats2half2_rn(pb[i].z, pb[i].w));
                *(uint2*)(sB + bOff[i]) = u;
            }
            if (MODE == 0) {
                #pragma unroll
                for (int i = 0; i < 4; ++i) {
                    uint2 u;
                    u.x = h2bits(__floats2half2_rn(pa[i].x, pa[i].y));
                    u.y = h2bits(__floats2half2_rn(pa[i].z, pa[i].w));
                    *(uint2*)(sA + aOff[i]) = u;
                }
            } else {
                #pragma unroll
                for (int i = 0; i < 2; ++i) *(uint4*)(sA + aOffH[i]) = qa[i];
            }
            __syncthreads();
        }
    }

    // ---- epilogue
    int r4 = lane >> 2, cc = (lane & 3) * 2;
    #pragma unroll
    for (int mi = 0; mi < 4; ++mi) {
        int row0 = m0 + mw + mi * 16 + r4;
        int row1 = row0 + 8;
        bool v0 = row0 < mEnd, v1 = row1 < mEnd;
        if (MODE == 0) {
            __half* C0 = g_h + (size_t)row0 * NTOT + n0;
            __half* C1 = g_h + (size_t)row1 * NTOT + n0;
            #pragma unroll
            for (int ni = 0; ni < 4; ++ni) {
                int col = nw + ni * 8 + cc;
                float bb0 = bias_s[col], bb1 = bias_s[col + 1];
                const float* d = acc[mi][ni];
                if (v0) {
                    __half2 h = __floats2half2_rn(fmaxf(d[0] + bb0, 0.f),
                                                  fmaxf(d[1] + bb1, 0.f));
                    *(__half2*)&C0[col] = h;
                }
                if (v1) {
                    __half2 h = __floats2half2_rn(fmaxf(d[2] + bb0, 0.f),
                                                  fmaxf(d[3] + bb1, 0.f));
                    *(__half2*)&C1[col] = h;
                }
            }
        } else {
            float w0 = 1.f, w1 = 1.f;
            if (v0) w0 = g_tw[g_perm[row0]];
            if (v1) w1 = g_tw[g_perm[row1]];
            float* C0 = g_contrib + (size_t)row0 * NTOT + n0;
            float* C1 = g_contrib + (size_t)row1 * NTOT + n0;
            #pragma unroll
            for (int ni = 0; ni < 4; ++ni) {
                int col = nw + ni * 8 + cc;
                float bb0 = bias_s[col], bb1 = bias_s[col + 1];
                const float* d = acc[mi][ni];
                if (v0) {
                    float2 o; o.x = (d[0] + bb0) * w0; o.y = (d[1] + bb1) * w0;
                    *(float2*)&C0[col] = o;
                }
                if (v1) {
                    float2 o; o.x = (d[2] + bb0) * w1; o.y = (d[3] + bb1) * w1;
                    *(float2*)&C1[col] = o;
                }
            }
        }
    }
}

// ---------------- combine ----------------------------------------------------
__global__ __launch_bounds__(256) void combine_kernel(float* __restrict__ out) {
    int idx = blockIdx.x * 256 + threadIdx.x;
    int tok = idx >> 8;
    int d4 = idx & 255;
    const float4* c0 = (const float4*)&g_contrib[(size_t)g_inv[tok * 2 + 0] * DOUT];
    const float4* c1 = (const float4*)&g_contrib[(size_t)g_inv[tok * 2 + 1] * DOUT];
    float4 a = c0[d4], b = c1[d4];
    float4 r;
    r.x = a.x + b.x; r.y = a.y + b.y; r.z = a.z + b.z; r.w = a.w + b.w;
    ((float4*)out)[idx] = r;
}

// ---------------- launch -----------------------------------------------------
extern "C" void kernel_launch(void* const* d_in, const int* in_sizes, int n_in,
                              void* d_out, int out_size) {
    const float* x  = (const float*)d_in[0];
    const float* gw = (const float*)d_in[1];
    const float* w1 = (const float*)d_in[2];
    const float* b1 = (const float*)d_in[3];
    const float* w2 = (const float*)d_in[4];
    const float* b2 = (const float*)d_in[5];
    float* out = (float*)d_out;

    init_kernel<<<1, 32>>>();
    gate_kernel<<<NB / 4, 128>>>(x, gw);
    prefix_kernel<<<1, 32>>>();
    scatter_kernel<<<NB / 256, 256>>>();
    gemm_tc<DI, DH, 0><<<dim3(DH / 128, MAXT), 256, GEMM_SMEM>>>(x, w1, b1);
    gemm_tc<DH, DOUT, 1><<<dim3(DOUT / 128, MAXT), 256, GEMM_SMEM>>>(nullptr, w2, b2);
    combine_kernel<<<NB * (DOUT / 4) / 256, 256>>>(out);
}